// round 8
// baseline (speedup 1.0000x reference)
#include <cuda_runtime.h>
#include <cuda_bf16.h>
#include <math.h>
#include <stdint.h>

// Problem constants
#define Bc 2
#define Lc 2048
#define Dc 1024
#define Hc 16
#define Dhc 64
#define Mg (Bc*Lc)          // 4096 rows
#define Ng (Hc*Dhc)         // 1024

// Scratch
__device__ float g_q[(size_t)Bc*Hc*Lc*Dhc];
__device__ float g_k[(size_t)Bc*Hc*Lc*Dhc];
__device__ float g_v[(size_t)Bc*Hc*Lc*Dhc];
__device__ float g_o[(size_t)Bc*Lc*Dc];

__device__ __forceinline__ uint32_t f2tf32(float f) {
    uint32_t u;
    asm("cvt.rna.tf32.f32 %0, %1;" : "=r"(u) : "f"(f));
    return u;
}

__device__ __forceinline__ void mma_tf32(float* c, const uint32_t* a, const uint32_t* b) {
    asm volatile(
        "mma.sync.aligned.m16n8k8.row.col.f32.tf32.tf32.f32 "
        "{%0,%1,%2,%3}, {%4,%5,%6,%7}, {%8,%9}, {%0,%1,%2,%3};"
        : "+f"(c[0]), "+f"(c[1]), "+f"(c[2]), "+f"(c[3])
        : "r"(a[0]), "r"(a[1]), "r"(a[2]), "r"(a[3]), "r"(b[0]), "r"(b[1]));
}

// ---------------------------------------------------------------------------
// TF32 tensor-core GEMM via mma.sync.  C[M,N] = A[M,K] * B[K,N], K=1024.
// Block 128x128, 8 warps (4x2), warp tile 32x64, k-chunk 32, double buffer.
// As[m][k] stride 36 (conflict-free frags), Bs[k][n] stride 136.
// mode 0: A=x, B=Wq/Wk/Wv (z), scatter into g_q/g_k/g_v [b][h][l][e]
// mode 1: A=g_o (device-side!), B=W0, plain row-major out
// ---------------------------------------------------------------------------
#define SA 36
#define SB 136
#define AS_FLOATS (128*SA)              // 4608
#define BS_FLOATS (32*SB)               // 4352
#define GEMM_SMEM ((2*AS_FLOATS + 2*BS_FLOATS) * 4)   // 71680 B

__global__ __launch_bounds__(256, 2)
void mma_gemm(const float* __restrict__ Ag_in,
              const float* __restrict__ W0, const float* __restrict__ W1,
              const float* __restrict__ W2,
              float* __restrict__ DstPlain, int mode)
{
    extern __shared__ float sm[];
    float* AsBuf[2] = { sm, sm + AS_FLOATS };
    float* BsBuf[2] = { sm + 2*AS_FLOATS, sm + 2*AS_FLOATS + BS_FLOATS };

    const int tid = threadIdx.x;
    const int lane = tid & 31, wid = tid >> 5;
    const int gid = lane >> 2, tig = lane & 3;
    const int wr = wid >> 1, wc = wid & 1;

    const int n0 = blockIdx.x * 128;
    const int m0 = blockIdx.y * 128;
    const int z  = blockIdx.z;

    // Device-side operand selection (NEVER pass __device__ symbols from host!)
    const float* Ag_base = (mode == 0) ? Ag_in : g_o;
    const float* Bw = (z == 0) ? W0 : (z == 1) ? W1 : W2;

    // LDG pointers
    const float* Agp = Ag_base + (size_t)(m0 + (tid >> 3)) * 1024 + (tid & 7) * 4;
    const float* Bgp = Bw + (size_t)(tid >> 5) * 1024 + n0 + (tid & 31) * 4;

    float4 aS[4], bS[4];

#define LDG_CHUNK(c) do { \
    _Pragma("unroll") \
    for (int i = 0; i < 4; i++) \
        aS[i] = *(const float4*)(Agp + (size_t)(c) * 32 + (size_t)i * 32 * 1024); \
    _Pragma("unroll") \
    for (int i = 0; i < 4; i++) \
        bS[i] = *(const float4*)(Bgp + (size_t)((c) * 32 + i * 8) * 1024); \
} while (0)

#define STS_CHUNK(buf) do { \
    float* as_ = AsBuf[buf]; float* bs_ = BsBuf[buf]; \
    const int am_ = tid >> 3, ak_ = (tid & 7) * 4; \
    _Pragma("unroll") \
    for (int i = 0; i < 4; i++) { \
        uint4 t_; \
        t_.x = f2tf32(aS[i].x); t_.y = f2tf32(aS[i].y); \
        t_.z = f2tf32(aS[i].z); t_.w = f2tf32(aS[i].w); \
        *(uint4*)(as_ + (am_ + 32*i) * SA + ak_) = t_; \
    } \
    const int bk_ = tid >> 5, bn_ = (tid & 31) * 4; \
    _Pragma("unroll") \
    for (int i = 0; i < 4; i++) { \
        uint4 t_; \
        t_.x = f2tf32(bS[i].x); t_.y = f2tf32(bS[i].y); \
        t_.z = f2tf32(bS[i].z); t_.w = f2tf32(bS[i].w); \
        *(uint4*)(bs_ + (bk_ + 8*i) * SB + bn_) = t_; \
    } \
} while (0)

    float c[2][8][4];
#pragma unroll
    for (int mi = 0; mi < 2; mi++)
#pragma unroll
        for (int ni = 0; ni < 8; ni++)
#pragma unroll
            for (int q = 0; q < 4; q++) c[mi][ni][q] = 0.f;

    LDG_CHUNK(0);
    STS_CHUNK(0);

    const int mbase = 32 * wr, nbase = 64 * wc;

    for (int ch = 0; ch < 32; ch++) {
        __syncthreads();                 // buffer (ch&1) ready, prior compute done
        if (ch < 31) LDG_CHUNK(ch + 1);

        const float* as = AsBuf[ch & 1];
        const float* bs = BsBuf[ch & 1];
#pragma unroll
        for (int ks = 0; ks < 4; ks++) {
            const int kk = ks * 8;
            uint32_t af[2][4];
#pragma unroll
            for (int mi = 0; mi < 2; mi++) {
                const int r0 = (mbase + 16*mi + gid) * SA + kk + tig;
                af[mi][0] = __float_as_uint(as[r0]);
                af[mi][1] = __float_as_uint(as[r0 + 8*SA]);
                af[mi][2] = __float_as_uint(as[r0 + 4]);
                af[mi][3] = __float_as_uint(as[r0 + 8*SA + 4]);
            }
            uint32_t bf[8][2];
#pragma unroll
            for (int ni = 0; ni < 8; ni++) {
                const int b0 = (kk + tig) * SB + nbase + 8*ni + gid;
                bf[ni][0] = __float_as_uint(bs[b0]);
                bf[ni][1] = __float_as_uint(bs[b0 + 4*SB]);
            }
#pragma unroll
            for (int mi = 0; mi < 2; mi++)
#pragma unroll
                for (int ni = 0; ni < 8; ni++)
                    mma_tf32(c[mi][ni], af[mi], bf[ni]);
        }

        if (ch < 31) {
            __syncthreads();             // all compute(ch) done before overwrite
            STS_CHUNK((ch + 1) & 1);
        }
    }

    // Epilogue
    float* gz = (mode == 0) ? ((z == 0) ? g_q : (z == 1) ? g_k : g_v) : DstPlain;
#pragma unroll
    for (int mi = 0; mi < 2; mi++) {
#pragma unroll
        for (int half = 0; half < 2; half++) {
            const int mloc = mbase + 16*mi + gid + 8*half;
            const int mglob = m0 + mloc;
#pragma unroll
            for (int ni = 0; ni < 8; ni++) {
                const int nglob = n0 + nbase + 8*ni + 2*tig;
                float2 v;
                v.x = c[mi][ni][2*half + 0];
                v.y = c[mi][ni][2*half + 1];
                if (mode == 0) {
                    const int b = mglob >> 11, l = mglob & 2047;
                    const int h = nglob >> 6, e = nglob & 63;
                    *(float2*)&gz[(((size_t)(b*Hc + h) * Lc + l) << 6) + e] = v;
                } else {
                    *(float2*)&gz[(size_t)mglob * 1024 + nglob] = v;
                }
            }
        }
    }
}

// ---------------------------------------------------------------------------
// Causal flash attention (unchanged: 64x64 tiles, fp32, conflict-free)
// ---------------------------------------------------------------------------
#define FL_SMEM (4 * 64 * 65 * 4)

__global__ __launch_bounds__(256, 3)
void flash_kernel()
{
    extern __shared__ float smf[];
    float* Qs = smf;
    float* Ks = smf + 64 * 65;
    float* Vs = smf + 2 * 64 * 65;
    float* Ps = smf + 3 * 64 * 65;
#define QS(r,c) Qs[(r)*65+(c)]
#define KS(r,c) Ks[(r)*65+(c)]
#define VS(r,c) Vs[(r)*65+(c)]
#define PS(r,c) Ps[(r)*65+(c)]

    const int qt = gridDim.x - 1 - blockIdx.x;  // heavy tiles first
    const int bh = blockIdx.y;
    const int tid = threadIdx.x;
    const int ty = tid >> 4, tx = tid & 15;

    const float* qb = g_q + (size_t)bh * Lc * Dhc;
    const float* kb = g_k + (size_t)bh * Lc * Dhc;
    const float* vb = g_v + (size_t)bh * Lc * Dhc;

    for (int i = tid; i < 64 * 64; i += 256) {
        int r = i >> 6, e = i & 63;
        QS(r, e) = qb[(size_t)(qt * 64 + r) * 64 + e];
    }

    float m_i[4], l_i[4], O[4][4];
#pragma unroll
    for (int i = 0; i < 4; i++) {
        m_i[i] = -3.0e38f;
        l_i[i] = 0.f;
#pragma unroll
        for (int j = 0; j < 4; j++) O[i][j] = 0.f;
    }

    for (int kt = 0; kt <= qt; kt++) {
        for (int i = tid; i < 64 * 64; i += 256) {
            int r = i >> 6, e = i & 63;
            KS(r, e) = kb[(size_t)(kt * 64 + r) * 64 + e];
            VS(r, e) = vb[(size_t)(kt * 64 + r) * 64 + e];
        }
        __syncthreads();

        float s[4][4];
#pragma unroll
        for (int i = 0; i < 4; i++)
#pragma unroll
            for (int j = 0; j < 4; j++) s[i][j] = 0.f;

#pragma unroll 8
        for (int e = 0; e < 64; e++) {
            float a[4], b[4];
#pragma unroll
            for (int i = 0; i < 4; i++) a[i] = QS(ty + 16 * i, e);
#pragma unroll
            for (int j = 0; j < 4; j++) b[j] = KS(tx + 16 * j, e);
#pragma unroll
            for (int i = 0; i < 4; i++)
#pragma unroll
                for (int j = 0; j < 4; j++)
                    s[i][j] += a[i] * b[j];
        }

        const float sc = 0.125f;
        if (kt == qt) {
#pragma unroll
            for (int i = 0; i < 4; i++)
#pragma unroll
                for (int j = 0; j < 4; j++)
                    s[i][j] = (tx + 16 * j > ty + 16 * i) ? -3.0e38f : s[i][j] * sc;
        } else {
#pragma unroll
            for (int i = 0; i < 4; i++)
#pragma unroll
                for (int j = 0; j < 4; j++)
                    s[i][j] *= sc;
        }

#pragma unroll
        for (int i = 0; i < 4; i++) {
            float rmax = fmaxf(fmaxf(s[i][0], s[i][1]), fmaxf(s[i][2], s[i][3]));
#pragma unroll
            for (int off = 8; off >= 1; off >>= 1)
                rmax = fmaxf(rmax, __shfl_xor_sync(0xffffffffu, rmax, off));
            float mnew = fmaxf(m_i[i], rmax);
            float corr = expf(m_i[i] - mnew);
            float rsum = 0.f;
#pragma unroll
            for (int j = 0; j < 4; j++) {
                s[i][j] = expf(s[i][j] - mnew);
                rsum += s[i][j];
            }
#pragma unroll
            for (int off = 8; off >= 1; off >>= 1)
                rsum += __shfl_xor_sync(0xffffffffu, rsum, off);
            l_i[i] = l_i[i] * corr + rsum;
            m_i[i] = mnew;
#pragma unroll
            for (int j = 0; j < 4; j++) O[i][j] *= corr;
#pragma unroll
            for (int j = 0; j < 4; j++)
                PS(ty + 16 * i, tx + 16 * j) = s[i][j];
        }
        __syncthreads();

#pragma unroll 8
        for (int jn = 0; jn < 64; jn++) {
            float pv[4], vv[4];
#pragma unroll
            for (int i = 0; i < 4; i++) pv[i] = PS(ty + 16 * i, jn);
#pragma unroll
            for (int j = 0; j < 4; j++) vv[j] = VS(jn, tx + 16 * j);
#pragma unroll
            for (int i = 0; i < 4; i++)
#pragma unroll
                for (int j = 0; j < 4; j++)
                    O[i][j] += pv[i] * vv[j];
        }
        __syncthreads();
    }

    const int bb = bh >> 4;
    const int h = bh & 15;
#pragma unroll
    for (int i = 0; i < 4; i++) {
        const int row = qt * 64 + ty + 16 * i;
        const float inv_l = 1.0f / l_i[i];
        size_t base = (size_t)(bb * Lc + row) * Dc + h * Dhc;
#pragma unroll
        for (int j = 0; j < 4; j++)
            g_o[base + tx + 16 * j] = O[i][j] * inv_l;
    }
}

// ---------------------------------------------------------------------------
extern "C" void kernel_launch(void* const* d_in, const int* in_sizes, int n_in,
                              void* d_out, int out_size)
{
    const float* x    = (const float*)d_in[0];
    const float* Wq   = (const float*)d_in[1];
    const float* Wk   = (const float*)d_in[2];
    const float* Wv   = (const float*)d_in[3];
    const float* Wout = (const float*)d_in[4];
    float* out = (float*)d_out;

    cudaFuncSetAttribute(mma_gemm,
                         cudaFuncAttributeMaxDynamicSharedMemorySize, GEMM_SMEM);
    cudaFuncSetAttribute(flash_kernel,
                         cudaFuncAttributeMaxDynamicSharedMemorySize, FL_SMEM);

    // QKV: C = x @ W_z, scattered into [b][h][l][e]
    mma_gemm<<<dim3(8, 32, 3), 256, GEMM_SMEM>>>(x, Wq, Wk, Wv, nullptr, 0);

    // Flash attention
    flash_kernel<<<dim3(Lc / 64, Bc * Hc), 256, FL_SMEM>>>();

    // Output projection: out = g_o @ Wout (A selected device-side)
    mma_gemm<<<dim3(8, 32, 1), 256, GEMM_SMEM>>>(nullptr, Wout, Wout, Wout, out, 1);
}

// round 9
// speedup vs baseline: 2.1509x; 2.1509x over previous
#include <cuda_runtime.h>
#include <cuda_bf16.h>
#include <math.h>
#include <stdint.h>

// Problem constants
#define Bc 2
#define Lc 2048
#define Dc 1024
#define Hc 16
#define Dhc 64
#define Mg (Bc*Lc)          // 4096 rows
#define Ng (Hc*Dhc)         // 1024

// Scratch
__device__ float g_q[(size_t)Bc*Hc*Lc*Dhc];
__device__ float g_k[(size_t)Bc*Hc*Lc*Dhc];
__device__ float g_v[(size_t)Bc*Hc*Lc*Dhc];
__device__ float g_o[(size_t)Bc*Lc*Dc];

__device__ __forceinline__ uint32_t f2tf32(float f) {
    uint32_t u;
    asm("cvt.rna.tf32.f32 %0, %1;" : "=r"(u) : "f"(f));
    return u;
}

__device__ __forceinline__ float ex2(float x) {
    float r;
    asm("ex2.approx.f32 %0, %1;" : "=f"(r) : "f"(x));
    return r;
}

__device__ __forceinline__ void mma_tf32(float* c, const uint32_t* a, const uint32_t* b) {
    asm volatile(
        "mma.sync.aligned.m16n8k8.row.col.f32.tf32.tf32.f32 "
        "{%0,%1,%2,%3}, {%4,%5,%6,%7}, {%8,%9}, {%0,%1,%2,%3};"
        : "+f"(c[0]), "+f"(c[1]), "+f"(c[2]), "+f"(c[3])
        : "r"(a[0]), "r"(a[1]), "r"(a[2]), "r"(a[3]), "r"(b[0]), "r"(b[1]));
}

// ---------------------------------------------------------------------------
// TF32 tensor-core GEMM via mma.sync.  C[M,N] = A[M,K] * B[K,N], K=1024.
// Block 128x128, 8 warps (4x2), warp tile 32x64, k-chunk 32, double buffer.
// mode 0: A=x, B=Wq/Wk/Wv (z), scatter into g_q/g_k/g_v [b][h][l][e]
// mode 1: A=g_o (device-side), B=W0, plain row-major out
// ---------------------------------------------------------------------------
#define SA 36
#define SB 136
#define AS_FLOATS (128*SA)
#define BS_FLOATS (32*SB)
#define GEMM_SMEM ((2*AS_FLOATS + 2*BS_FLOATS) * 4)   // 71680 B

__global__ __launch_bounds__(256, 2)
void mma_gemm(const float* __restrict__ Ag_in,
              const float* __restrict__ W0, const float* __restrict__ W1,
              const float* __restrict__ W2,
              float* __restrict__ DstPlain, int mode)
{
    extern __shared__ float sm[];
    float* AsBuf[2] = { sm, sm + AS_FLOATS };
    float* BsBuf[2] = { sm + 2*AS_FLOATS, sm + 2*AS_FLOATS + BS_FLOATS };

    const int tid = threadIdx.x;
    const int lane = tid & 31, wid = tid >> 5;
    const int gid = lane >> 2, tig = lane & 3;
    const int wr = wid >> 1, wc = wid & 1;

    const int n0 = blockIdx.x * 128;
    const int m0 = blockIdx.y * 128;
    const int z  = blockIdx.z;

    const float* Ag_base = (mode == 0) ? Ag_in : g_o;
    const float* Bw = (z == 0) ? W0 : (z == 1) ? W1 : W2;

    const float* Agp = Ag_base + (size_t)(m0 + (tid >> 3)) * 1024 + (tid & 7) * 4;
    const float* Bgp = Bw + (size_t)(tid >> 5) * 1024 + n0 + (tid & 31) * 4;

    float4 aS[4], bS[4];

#define LDG_CHUNK(c) do { \
    _Pragma("unroll") \
    for (int i = 0; i < 4; i++) \
        aS[i] = *(const float4*)(Agp + (size_t)(c) * 32 + (size_t)i * 32 * 1024); \
    _Pragma("unroll") \
    for (int i = 0; i < 4; i++) \
        bS[i] = *(const float4*)(Bgp + (size_t)((c) * 32 + i * 8) * 1024); \
} while (0)

#define STS_CHUNK(buf) do { \
    float* as_ = AsBuf[buf]; float* bs_ = BsBuf[buf]; \
    const int am_ = tid >> 3, ak_ = (tid & 7) * 4; \
    _Pragma("unroll") \
    for (int i = 0; i < 4; i++) { \
        uint4 t_; \
        t_.x = f2tf32(aS[i].x); t_.y = f2tf32(aS[i].y); \
        t_.z = f2tf32(aS[i].z); t_.w = f2tf32(aS[i].w); \
        *(uint4*)(as_ + (am_ + 32*i) * SA + ak_) = t_; \
    } \
    const int bk_ = tid >> 5, bn_ = (tid & 31) * 4; \
    _Pragma("unroll") \
    for (int i = 0; i < 4; i++) { \
        uint4 t_; \
        t_.x = f2tf32(bS[i].x); t_.y = f2tf32(bS[i].y); \
        t_.z = f2tf32(bS[i].z); t_.w = f2tf32(bS[i].w); \
        *(uint4*)(bs_ + (bk_ + 8*i) * SB + bn_) = t_; \
    } \
} while (0)

    float c[2][8][4];
#pragma unroll
    for (int mi = 0; mi < 2; mi++)
#pragma unroll
        for (int ni = 0; ni < 8; ni++)
#pragma unroll
            for (int q = 0; q < 4; q++) c[mi][ni][q] = 0.f;

    LDG_CHUNK(0);
    STS_CHUNK(0);

    const int mbase = 32 * wr, nbase = 64 * wc;

    for (int ch = 0; ch < 32; ch++) {
        __syncthreads();
        if (ch < 31) LDG_CHUNK(ch + 1);

        const float* as = AsBuf[ch & 1];
        const float* bs = BsBuf[ch & 1];
#pragma unroll
        for (int ks = 0; ks < 4; ks++) {
            const int kk = ks * 8;
            uint32_t af[2][4];
#pragma unroll
            for (int mi = 0; mi < 2; mi++) {
                const int r0 = (mbase + 16*mi + gid) * SA + kk + tig;
                af[mi][0] = __float_as_uint(as[r0]);
                af[mi][1] = __float_as_uint(as[r0 + 8*SA]);
                af[mi][2] = __float_as_uint(as[r0 + 4]);
                af[mi][3] = __float_as_uint(as[r0 + 8*SA + 4]);
            }
            uint32_t bf[8][2];
#pragma unroll
            for (int ni = 0; ni < 8; ni++) {
                const int b0 = (kk + tig) * SB + nbase + 8*ni + gid;
                bf[ni][0] = __float_as_uint(bs[b0]);
                bf[ni][1] = __float_as_uint(bs[b0 + 4*SB]);
            }
#pragma unroll
            for (int mi = 0; mi < 2; mi++)
#pragma unroll
                for (int ni = 0; ni < 8; ni++)
                    mma_tf32(c[mi][ni], af[mi], bf[ni]);
        }

        if (ch < 31) {
            __syncthreads();
            STS_CHUNK((ch + 1) & 1);
        }
    }

    float* gz = (mode == 0) ? ((z == 0) ? g_q : (z == 1) ? g_k : g_v) : DstPlain;
#pragma unroll
    for (int mi = 0; mi < 2; mi++) {
#pragma unroll
        for (int half = 0; half < 2; half++) {
            const int mloc = mbase + 16*mi + gid + 8*half;
            const int mglob = m0 + mloc;
#pragma unroll
            for (int ni = 0; ni < 8; ni++) {
                const int nglob = n0 + nbase + 8*ni + 2*tig;
                float2 v;
                v.x = c[mi][ni][2*half + 0];
                v.y = c[mi][ni][2*half + 1];
                if (mode == 0) {
                    const int b = mglob >> 11, l = mglob & 2047;
                    const int h = nglob >> 6, e = nglob & 63;
                    *(float2*)&gz[(((size_t)(b*Hc + h) * Lc + l) << 6) + e] = v;
                } else {
                    *(float2*)&gz[(size_t)mglob * 1024 + nglob] = v;
                }
            }
        }
    }
}

// ---------------------------------------------------------------------------
// TF32 tensor-core causal flash attention.
// Block: 128 q-rows (8 warps x 16), K-tile 64. All operands tf32 in smem.
// Strides: Q/K/P 68 (bank=4g+t bijective), V 72 (bank=8t+g bijective).
// Scale 1/8 and log2(e) folded into Q at load; softmax uses ex2.approx.
// ---------------------------------------------------------------------------
#define SQf 68
#define SKf 68
#define SVf 72
#define SPf 68
#define QS_OFF 0
#define KS_OFF (128*SQf)                 // 8704
#define VS_OFF (KS_OFF + 64*SKf)         // 13056
#define PS_OFF (VS_OFF + 64*SVf)         // 17664
#define FL_FLOATS (PS_OFF + 128*SPf)     // 26368
#define FL_SMEM (FL_FLOATS * 4)          // 105472 B

__global__ __launch_bounds__(256, 2)
void flash_kernel()
{
    extern __shared__ float sm[];
    float* Qs = sm + QS_OFF;
    float* Ks = sm + KS_OFF;
    float* Vs = sm + VS_OFF;
    float* Ps = sm + PS_OFF;

    const int qt = gridDim.x - 1 - blockIdx.x;   // heavy tiles first
    const int bh = blockIdx.y;
    const int tid = threadIdx.x;
    const int lane = tid & 31, wid = tid >> 5;
    const int g = lane >> 2, t = lane & 3;
    const int wq0 = wid * 16;

    const float* qb = g_q + (size_t)bh * Lc * Dhc;
    const float* kb = g_k + (size_t)bh * Lc * Dhc;
    const float* vb = g_v + (size_t)bh * Lc * Dhc;

    const float QSCALE = 0.18033688011112042f;   // (1/8) * log2(e)

    // Load Q tile (128 x 64), scaled + tf32
#pragma unroll
    for (int it = 0; it < 8; it++) {
        const int idx = it * 256 + tid;
        const int r = idx >> 4, c4 = (idx & 15) * 4;
        float4 v = *(const float4*)(qb + (size_t)(qt * 128 + r) * 64 + c4);
        uint4 u;
        u.x = f2tf32(v.x * QSCALE); u.y = f2tf32(v.y * QSCALE);
        u.z = f2tf32(v.z * QSCALE); u.w = f2tf32(v.w * QSCALE);
        *(uint4*)(Qs + r * SQf + c4) = u;
    }

    float m2[2] = {-1e30f, -1e30f};
    float lsum[2] = {0.f, 0.f};
    float o[8][4];
#pragma unroll
    for (int ni = 0; ni < 8; ni++)
#pragma unroll
        for (int q = 0; q < 4; q++) o[ni][q] = 0.f;

    const int kend = 2 * qt + 1;
    for (int kt = 0; kt <= kend; kt++) {
        __syncthreads();   // prior iter's K/V reads done (and Q store on iter 0)
        // Load K, V tiles (64 x 64 each), tf32
#pragma unroll
        for (int it = 0; it < 4; it++) {
            const int idx = it * 256 + tid;
            const int r = idx >> 4, c4 = (idx & 15) * 4;
            float4 kv = *(const float4*)(kb + (size_t)(kt * 64 + r) * 64 + c4);
            uint4 uk;
            uk.x = f2tf32(kv.x); uk.y = f2tf32(kv.y);
            uk.z = f2tf32(kv.z); uk.w = f2tf32(kv.w);
            *(uint4*)(Ks + r * SKf + c4) = uk;
            float4 vv = *(const float4*)(vb + (size_t)(kt * 64 + r) * 64 + c4);
            uint4 uv;
            uv.x = f2tf32(vv.x); uv.y = f2tf32(vv.y);
            uv.z = f2tf32(vv.z); uv.w = f2tf32(vv.w);
            *(uint4*)(Vs + r * SVf + c4) = uv;
        }
        __syncthreads();

        // S = Q K^T  (warp: 16 x 64, k=64)
        float s[8][4];
#pragma unroll
        for (int ni = 0; ni < 8; ni++)
#pragma unroll
            for (int q = 0; q < 4; q++) s[ni][q] = 0.f;

#pragma unroll
        for (int ks = 0; ks < 8; ks++) {
            const int k0 = ks * 8;
            uint32_t a[4];
            a[0] = __float_as_uint(Qs[(wq0 + g) * SQf + k0 + t]);
            a[1] = __float_as_uint(Qs[(wq0 + g + 8) * SQf + k0 + t]);
            a[2] = __float_as_uint(Qs[(wq0 + g) * SQf + k0 + t + 4]);
            a[3] = __float_as_uint(Qs[(wq0 + g + 8) * SQf + k0 + t + 4]);
#pragma unroll
            for (int ni = 0; ni < 8; ni++) {
                uint32_t b[2];
                b[0] = __float_as_uint(Ks[(ni * 8 + g) * SKf + k0 + t]);
                b[1] = __float_as_uint(Ks[(ni * 8 + g) * SKf + k0 + t + 4]);
                mma_tf32(s[ni], a, b);
            }
        }

        // Causal mask (only near-diagonal kt tiles)
        if (kt >= 2 * qt) {
            const int q0r = qt * 128 + wq0 + g;
#pragma unroll
            for (int ni = 0; ni < 8; ni++) {
                const int key0 = kt * 64 + ni * 8 + 2 * t;
                if (key0     > q0r)     s[ni][0] = -1e30f;
                if (key0 + 1 > q0r)     s[ni][1] = -1e30f;
                if (key0     > q0r + 8) s[ni][2] = -1e30f;
                if (key0 + 1 > q0r + 8) s[ni][3] = -1e30f;
            }
        }

        // Online softmax (rows g and g+8; reduce over tig via shfl)
        __syncwarp();   // previous PV reads of Ps complete before overwrite
#pragma unroll
        for (int rr = 0; rr < 2; rr++) {
            float mx = -1e30f;
#pragma unroll
            for (int ni = 0; ni < 8; ni++)
                mx = fmaxf(mx, fmaxf(s[ni][2*rr], s[ni][2*rr + 1]));
            mx = fmaxf(mx, __shfl_xor_sync(0xffffffffu, mx, 1));
            mx = fmaxf(mx, __shfl_xor_sync(0xffffffffu, mx, 2));
            const float mnew = fmaxf(m2[rr], mx);
            const float corr = ex2(m2[rr] - mnew);
            float rs = 0.f;
#pragma unroll
            for (int ni = 0; ni < 8; ni++) {
                const float p0 = ex2(s[ni][2*rr]     - mnew);
                const float p1 = ex2(s[ni][2*rr + 1] - mnew);
                rs += p0 + p1;
                uint2 pw;
                pw.x = f2tf32(p0); pw.y = f2tf32(p1);
                *(uint2*)(Ps + (wq0 + g + 8*rr) * SPf + ni * 8 + 2 * t) = pw;
            }
            rs += __shfl_xor_sync(0xffffffffu, rs, 1);
            rs += __shfl_xor_sync(0xffffffffu, rs, 2);
            lsum[rr] = lsum[rr] * corr + rs;
            m2[rr] = mnew;
#pragma unroll
            for (int ni = 0; ni < 8; ni++) {
                o[ni][2*rr]     *= corr;
                o[ni][2*rr + 1] *= corr;
            }
        }
        __syncwarp();

        // O += P V  (warp: 16 x 64, k=64 keys)
#pragma unroll
        for (int ks = 0; ks < 8; ks++) {
            const int k0 = ks * 8;
            uint32_t a[4];
            a[0] = __float_as_uint(Ps[(wq0 + g) * SPf + k0 + t]);
            a[1] = __float_as_uint(Ps[(wq0 + g + 8) * SPf + k0 + t]);
            a[2] = __float_as_uint(Ps[(wq0 + g) * SPf + k0 + t + 4]);
            a[3] = __float_as_uint(Ps[(wq0 + g + 8) * SPf + k0 + t + 4]);
#pragma unroll
            for (int ni = 0; ni < 8; ni++) {
                uint32_t b[2];
                b[0] = __float_as_uint(Vs[(k0 + t) * SVf + ni * 8 + g]);
                b[1] = __float_as_uint(Vs[(k0 + t + 4) * SVf + ni * 8 + g]);
                mma_tf32(o[ni], a, b);
            }
        }
    }

    // Epilogue: normalize and write to g_o [b][l][h*64+e]
    const float inv0 = 1.0f / lsum[0];
    const float inv1 = 1.0f / lsum[1];
    const int b = bh >> 4, h = bh & 15;
    const int q0 = qt * 128 + wq0 + g;
    const size_t base0 = ((size_t)(b * Lc + q0)) * Dc + h * Dhc;
    const size_t base1 = base0 + (size_t)8 * Dc;
#pragma unroll
    for (int ni = 0; ni < 8; ni++) {
        float2 v0, v1;
        v0.x = o[ni][0] * inv0; v0.y = o[ni][1] * inv0;
        v1.x = o[ni][2] * inv1; v1.y = o[ni][3] * inv1;
        *(float2*)&g_o[base0 + ni * 8 + 2 * t] = v0;
        *(float2*)&g_o[base1 + ni * 8 + 2 * t] = v1;
    }
}

// ---------------------------------------------------------------------------
extern "C" void kernel_launch(void* const* d_in, const int* in_sizes, int n_in,
                              void* d_out, int out_size)
{
    const float* x    = (const float*)d_in[0];
    const float* Wq   = (const float*)d_in[1];
    const float* Wk   = (const float*)d_in[2];
    const float* Wv   = (const float*)d_in[3];
    const float* Wout = (const float*)d_in[4];
    float* out = (float*)d_out;

    cudaFuncSetAttribute(mma_gemm,
                         cudaFuncAttributeMaxDynamicSharedMemorySize, GEMM_SMEM);
    cudaFuncSetAttribute(flash_kernel,
                         cudaFuncAttributeMaxDynamicSharedMemorySize, FL_SMEM);

    // QKV: C = x @ W_z, scattered into [b][h][l][e]
    mma_gemm<<<dim3(8, 32, 3), 256, GEMM_SMEM>>>(x, Wq, Wk, Wv, nullptr, 0);

    // Flash attention (tf32 tensor cores)
    flash_kernel<<<dim3(Lc / 128, Bc * Hc), 256, FL_SMEM>>>();

    // Output projection: out = g_o @ Wout
    mma_gemm<<<dim3(8, 32, 1), 256, GEMM_SMEM>>>(nullptr, Wout, Wout, Wout, out, 1);
}

// round 10
// speedup vs baseline: 3.6939x; 1.7174x over previous
#include <cuda_runtime.h>
#include <math.h>
#include <stdint.h>

// Problem constants
#define Bc 2
#define Lc 2048
#define Dc 1024
#define Hc 16
#define Dhc 64
#define Mg (Bc*Lc)          // 4096

// Scratch
__device__ float g_q[(size_t)Bc*Hc*Lc*Dhc];
__device__ float g_k[(size_t)Bc*Hc*Lc*Dhc];
__device__ float g_v[(size_t)Bc*Hc*Lc*Dhc];
__device__ float g_o[(size_t)Bc*Lc*Dc];
__device__ float g_xc[(size_t)Mg*Dc];        // x, tf32-rounded
__device__ float g_wc[(size_t)4*Dc*Dc];      // W{q,k,v,o}, tf32-rounded (Wq pre-scaled)

// ---------------------------------------------------------------------------
// Helpers
// ---------------------------------------------------------------------------
__device__ __forceinline__ uint32_t f2tf32(float f) {
    uint32_t u;
    asm("cvt.rna.tf32.f32 %0, %1;" : "=r"(u) : "f"(f));
    return u;
}

__device__ __forceinline__ float ex2(float x) {
    float r;
    asm("ex2.approx.f32 %0, %1;" : "=f"(r) : "f"(x));
    return r;
}

__device__ __forceinline__ uint32_t smem_u32(const void* p) {
    uint32_t a;
    asm("{ .reg .u64 t; cvta.to.shared.u64 t, %1; cvt.u32.u64 %0, t; }"
        : "=r"(a) : "l"(p));
    return a;
}

__device__ __forceinline__ void cpa16(uint32_t s, const void* g) {
    asm volatile("cp.async.cg.shared.global [%0], [%1], 16;" :: "r"(s), "l"(g));
}
#define CP_COMMIT() asm volatile("cp.async.commit_group;" ::: "memory")
#define CP_WAIT(n)  asm volatile("cp.async.wait_group %0;" :: "n"(n) : "memory")

__device__ __forceinline__ void mma_tf32(float* c, const uint32_t* a, const uint32_t* b) {
    asm volatile(
        "mma.sync.aligned.m16n8k8.row.col.f32.tf32.tf32.f32 "
        "{%0,%1,%2,%3}, {%4,%5,%6,%7}, {%8,%9}, {%0,%1,%2,%3};"
        : "+f"(c[0]), "+f"(c[1]), "+f"(c[2]), "+f"(c[3])
        : "r"(a[0]), "r"(a[1]), "r"(a[2]), "r"(a[3]), "r"(b[0]), "r"(b[1]));
}

// ---------------------------------------------------------------------------
// Prep: tf32-round x and weights once. Wq gets (1/8)*log2(e) folded in.
// ---------------------------------------------------------------------------
__global__ __launch_bounds__(256)
void prep_kernel(const float* __restrict__ x, const float* __restrict__ Wq,
                 const float* __restrict__ Wk, const float* __restrict__ Wv,
                 const float* __restrict__ Wo)
{
    const int y = blockIdx.y;
    const float* src;
    float* dst;
    size_t n;
    float scale = 1.0f;
    if (y == 0) { src = x; dst = g_xc; n = (size_t)Mg * Dc; }
    else {
        src = (y == 1) ? Wq : (y == 2) ? Wk : (y == 3) ? Wv : Wo;
        dst = g_wc + (size_t)(y - 1) * 1048576;
        n = 1048576;
        if (y == 1) scale = 0.18033688011112042f;   // (1/8)*log2(e)
    }
    const size_t stride = (size_t)gridDim.x * 256 * 4;
    for (size_t i = ((size_t)blockIdx.x * 256 + threadIdx.x) * 4; i < n; i += stride) {
        float4 v = *(const float4*)(src + i);
        uint4 u;
        u.x = f2tf32(v.x * scale); u.y = f2tf32(v.y * scale);
        u.z = f2tf32(v.z * scale); u.w = f2tf32(v.w * scale);
        *(uint4*)(dst + i) = u;
    }
}

// ---------------------------------------------------------------------------
// cp.async 3-stage pipelined TF32 GEMM. C[M,N] = A[M,K]*B[K,N], K=1024.
// Block 128x128, 8 warps (4x2), warp tile 32x64, k-chunk 32.
// Operands are pre-rounded tf32 -> zero conversions in the hot loop.
// mode 0: A=g_xc, B=g_wc[z], scatter tf32-rounded into g_q/g_k/g_v
// mode 1: A=g_o,  B=g_wc[3], plain fp32 row-major out
// ---------------------------------------------------------------------------
#define SA 36
#define SB 136
#define A_ST_FL (128*SA)                 // 4608 floats
#define B_ST_FL (32*SB)                  // 4352 floats
#define STG_FL  (A_ST_FL + B_ST_FL)      // 8960
#define STG_BYTES (STG_FL*4)             // 35840
#define GEMM_SMEM (3*STG_BYTES)          // 107520 B

__global__ __launch_bounds__(256, 2)
void mma_gemm(float* __restrict__ Dst, int mode)
{
    extern __shared__ float sm[];
    const uint32_t sb = smem_u32(sm);

    const int tid = threadIdx.x;
    const int lane = tid & 31, wid = tid >> 5;
    const int g = lane >> 2, t = lane & 3;
    const int wr = wid >> 1, wc = wid & 1;

    const int n0 = blockIdx.x * 128;
    const int m0 = blockIdx.y * 128;
    const int z  = blockIdx.z;

    const float* A = (mode == 0) ? g_xc : g_o;
    const float* B = g_wc + (size_t)((mode == 0) ? z : 3) * 1048576;

    const float* Agp = A + (size_t)(m0 + (tid >> 3)) * 1024 + (tid & 7) * 4;
    const float* Bgp = B + (size_t)(tid >> 5) * 1024 + n0 + (tid & 31) * 4;

    const uint32_t aoff = (uint32_t)(tid >> 3) * (SA * 4) + (tid & 7) * 16;
    const uint32_t boff = (uint32_t)(A_ST_FL * 4) + (uint32_t)(tid >> 5) * (SB * 4)
                        + (tid & 31) * 16;

#define G_ISSUE(ch) do { \
    const uint32_t st_ = sb + (uint32_t)((ch) % 3) * STG_BYTES; \
    const float* ag_ = Agp + (ch) * 32; \
    const float* bg_ = Bgp + (size_t)(ch) * 32 * 1024; \
    _Pragma("unroll") \
    for (int i_ = 0; i_ < 4; i_++) \
        cpa16(st_ + aoff + i_ * 32 * (SA * 4), ag_ + (size_t)i_ * 32 * 1024); \
    _Pragma("unroll") \
    for (int i_ = 0; i_ < 4; i_++) \
        cpa16(st_ + boff + i_ * 8 * (SB * 4), bg_ + (size_t)i_ * 8 * 1024); \
} while (0)

    float c[2][8][4];
#pragma unroll
    for (int mi = 0; mi < 2; mi++)
#pragma unroll
        for (int ni = 0; ni < 8; ni++)
#pragma unroll
            for (int q = 0; q < 4; q++) c[mi][ni][q] = 0.f;

    G_ISSUE(0); CP_COMMIT();
    G_ISSUE(1); CP_COMMIT();

    const int mbase = 32 * wr, nbase = 64 * wc;

    for (int ch = 0; ch < 32; ch++) {
        CP_WAIT(1);
        __syncthreads();                 // stage ch data visible to all
        if (ch + 2 < 32) G_ISSUE(ch + 2);   // into buffer (ch-1)%3, fully consumed
        CP_COMMIT();

        const float* as = sm + (ch % 3) * STG_FL;
        const float* bs = as + A_ST_FL;
#pragma unroll
        for (int ks = 0; ks < 4; ks++) {
            const int kk = ks * 8;
            uint32_t af[2][4];
#pragma unroll
            for (int mi = 0; mi < 2; mi++) {
                const int r0 = (mbase + 16*mi + g) * SA + kk + t;
                af[mi][0] = __float_as_uint(as[r0]);
                af[mi][1] = __float_as_uint(as[r0 + 8*SA]);
                af[mi][2] = __float_as_uint(as[r0 + 4]);
                af[mi][3] = __float_as_uint(as[r0 + 8*SA + 4]);
            }
            uint32_t bf[8][2];
#pragma unroll
            for (int ni = 0; ni < 8; ni++) {
                const int b0 = (kk + t) * SB + nbase + 8*ni + g;
                bf[ni][0] = __float_as_uint(bs[b0]);
                bf[ni][1] = __float_as_uint(bs[b0 + 4*SB]);
            }
#pragma unroll
            for (int mi = 0; mi < 2; mi++)
#pragma unroll
                for (int ni = 0; ni < 8; ni++)
                    mma_tf32(c[mi][ni], af[mi], bf[ni]);
        }
    }

    // Epilogue. mode 0: tf32-round (consumers feed mma directly).
    float* gz = (mode == 0) ? ((z == 0) ? g_q : (z == 1) ? g_k : g_v) : Dst;
#pragma unroll
    for (int mi = 0; mi < 2; mi++) {
#pragma unroll
        for (int half = 0; half < 2; half++) {
            const int mglob = m0 + mbase + 16*mi + g + 8*half;
#pragma unroll
            for (int ni = 0; ni < 8; ni++) {
                const int nglob = n0 + nbase + 8*ni + 2*t;
                float2 v;
                v.x = c[mi][ni][2*half + 0];
                v.y = c[mi][ni][2*half + 1];
                if (mode == 0) {
                    v.x = __uint_as_float(f2tf32(v.x));
                    v.y = __uint_as_float(f2tf32(v.y));
                    const int b = mglob >> 11, l = mglob & 2047;
                    const int h = nglob >> 6, e = nglob & 63;
                    *(float2*)&gz[(((size_t)(b*Hc + h) * Lc + l) << 6) + e] = v;
                } else {
                    *(float2*)&gz[(size_t)mglob * 1024 + nglob] = v;
                }
            }
        }
    }
}

// ---------------------------------------------------------------------------
// TF32 tensor-core causal flash attention. Inputs are pre-rounded tf32
// (Q pre-scaled via Wq) -> loads are straight cp.async copies.
// Block: 128 q-rows (8 warps x 16), K-tile 64.
// ---------------------------------------------------------------------------
#define SQf 68
#define SKf 68
#define SVf 72
#define SPf 68
#define QS_OFF 0
#define KS_OFF (128*SQf)                 // 8704
#define VS_OFF (KS_OFF + 64*SKf)         // 13056
#define PS_OFF (VS_OFF + 64*SVf)         // 17664
#define FL_FLOATS (PS_OFF + 128*SPf)     // 26368
#define FL_SMEM (FL_FLOATS * 4)          // 105472 B

__global__ __launch_bounds__(256, 2)
void flash_kernel()
{
    extern __shared__ float sm[];
    const uint32_t sb = smem_u32(sm);
    float* Qs = sm + QS_OFF;
    float* Ks = sm + KS_OFF;
    float* Vs = sm + VS_OFF;
    float* Ps = sm + PS_OFF;

    const int qt = gridDim.x - 1 - blockIdx.x;   // heavy tiles first
    const int bh = blockIdx.y;
    const int tid = threadIdx.x;
    const int lane = tid & 31, wid = tid >> 5;
    const int g = lane >> 2, t = lane & 3;
    const int wq0 = wid * 16;

    const float* qb = g_q + (size_t)bh * Lc * Dhc;
    const float* kb = g_k + (size_t)bh * Lc * Dhc;
    const float* vb = g_v + (size_t)bh * Lc * Dhc;

    // Q tile (128 x 64) via cp.async (already scaled + tf32)
#pragma unroll
    for (int it = 0; it < 8; it++) {
        const int idx = it * 256 + tid;
        const int r = idx >> 4, c4 = (idx & 15) * 4;
        cpa16(sb + (uint32_t)(r * SQf + c4) * 4,
              qb + (size_t)(qt * 128 + r) * 64 + c4);
    }
    CP_COMMIT();

    float m2[2] = {-1e30f, -1e30f};
    float lsum[2] = {0.f, 0.f};
    float o[8][4];
#pragma unroll
    for (int ni = 0; ni < 8; ni++)
#pragma unroll
        for (int q = 0; q < 4; q++) o[ni][q] = 0.f;

    const int kend = 2 * qt + 1;
    for (int kt = 0; kt <= kend; kt++) {
        __syncthreads();   // prior iter's K/V reads complete
#pragma unroll
        for (int it = 0; it < 4; it++) {
            const int idx = it * 256 + tid;
            const int r = idx >> 4, c4 = (idx & 15) * 4;
            cpa16(sb + (uint32_t)(KS_OFF + r * SKf + c4) * 4,
                  kb + (size_t)(kt * 64 + r) * 64 + c4);
            cpa16(sb + (uint32_t)(VS_OFF + r * SVf + c4) * 4,
                  vb + (size_t)(kt * 64 + r) * 64 + c4);
        }
        CP_COMMIT();
        CP_WAIT(0);
        __syncthreads();

        // S = Q K^T  (warp: 16 x 64, k=64)
        float s[8][4];
#pragma unroll
        for (int ni = 0; ni < 8; ni++)
#pragma unroll
            for (int q = 0; q < 4; q++) s[ni][q] = 0.f;

#pragma unroll
        for (int ks = 0; ks < 8; ks++) {
            const int k0 = ks * 8;
            uint32_t a[4];
            a[0] = __float_as_uint(Qs[(wq0 + g) * SQf + k0 + t]);
            a[1] = __float_as_uint(Qs[(wq0 + g + 8) * SQf + k0 + t]);
            a[2] = __float_as_uint(Qs[(wq0 + g) * SQf + k0 + t + 4]);
            a[3] = __float_as_uint(Qs[(wq0 + g + 8) * SQf + k0 + t + 4]);
#pragma unroll
            for (int ni = 0; ni < 8; ni++) {
                uint32_t b[2];
                b[0] = __float_as_uint(Ks[(ni * 8 + g) * SKf + k0 + t]);
                b[1] = __float_as_uint(Ks[(ni * 8 + g) * SKf + k0 + t + 4]);
                mma_tf32(s[ni], a, b);
            }
        }

        // Causal mask (near-diagonal tiles only)
        if (kt >= 2 * qt) {
            const int q0r = qt * 128 + wq0 + g;
#pragma unroll
            for (int ni = 0; ni < 8; ni++) {
                const int key0 = kt * 64 + ni * 8 + 2 * t;
                if (key0     > q0r)     s[ni][0] = -1e30f;
                if (key0 + 1 > q0r)     s[ni][1] = -1e30f;
                if (key0     > q0r + 8) s[ni][2] = -1e30f;
                if (key0 + 1 > q0r + 8) s[ni][3] = -1e30f;
            }
        }

        // Online softmax (rows g, g+8; reduce over t-lanes via shfl)
        __syncwarp();   // prior PV reads of Ps done before overwrite
#pragma unroll
        for (int rr = 0; rr < 2; rr++) {
            float mx = -1e30f;
#pragma unroll
            for (int ni = 0; ni < 8; ni++)
                mx = fmaxf(mx, fmaxf(s[ni][2*rr], s[ni][2*rr + 1]));
            mx = fmaxf(mx, __shfl_xor_sync(0xffffffffu, mx, 1));
            mx = fmaxf(mx, __shfl_xor_sync(0xffffffffu, mx, 2));
            const float mnew = fmaxf(m2[rr], mx);
            const float corr = ex2(m2[rr] - mnew);
            float rs = 0.f;
#pragma unroll
            for (int ni = 0; ni < 8; ni++) {
                const float p0 = ex2(s[ni][2*rr]     - mnew);
                const float p1 = ex2(s[ni][2*rr + 1] - mnew);
                rs += p0 + p1;
                uint2 pw;
                pw.x = f2tf32(p0); pw.y = f2tf32(p1);
                *(uint2*)(Ps + (wq0 + g + 8*rr) * SPf + ni * 8 + 2 * t) = pw;
            }
            rs += __shfl_xor_sync(0xffffffffu, rs, 1);
            rs += __shfl_xor_sync(0xffffffffu, rs, 2);
            lsum[rr] = lsum[rr] * corr + rs;
            m2[rr] = mnew;
#pragma unroll
            for (int ni = 0; ni < 8; ni++) {
                o[ni][2*rr]     *= corr;
                o[ni][2*rr + 1] *= corr;
            }
        }
        __syncwarp();

        // O += P V
#pragma unroll
        for (int ks = 0; ks < 8; ks++) {
            const int k0 = ks * 8;
            uint32_t a[4];
            a[0] = __float_as_uint(Ps[(wq0 + g) * SPf + k0 + t]);
            a[1] = __float_as_uint(Ps[(wq0 + g + 8) * SPf + k0 + t]);
            a[2] = __float_as_uint(Ps[(wq0 + g) * SPf + k0 + t + 4]);
            a[3] = __float_as_uint(Ps[(wq0 + g + 8) * SPf + k0 + t + 4]);
#pragma unroll
            for (int ni = 0; ni < 8; ni++) {
                uint32_t b[2];
                b[0] = __float_as_uint(Vs[(k0 + t) * SVf + ni * 8 + g]);
                b[1] = __float_as_uint(Vs[(k0 + t + 4) * SVf + ni * 8 + g]);
                mma_tf32(o[ni], a, b);
            }
        }
    }

    // Epilogue: normalize, tf32-round (feeds out-proj mma), write g_o
    const float inv0 = 1.0f / lsum[0];
    const float inv1 = 1.0f / lsum[1];
    const int b = bh >> 4, h = bh & 15;
    const int q0 = qt * 128 + wq0 + g;
    const size_t base0 = ((size_t)(b * Lc + q0)) * Dc + h * Dhc;
    const size_t base1 = base0 + (size_t)8 * Dc;
#pragma unroll
    for (int ni = 0; ni < 8; ni++) {
        float2 v0, v1;
        v0.x = __uint_as_float(f2tf32(o[ni][0] * inv0));
        v0.y = __uint_as_float(f2tf32(o[ni][1] * inv0));
        v1.x = __uint_as_float(f2tf32(o[ni][2] * inv1));
        v1.y = __uint_as_float(f2tf32(o[ni][3] * inv1));
        *(float2*)&g_o[base0 + ni * 8 + 2 * t] = v0;
        *(float2*)&g_o[base1 + ni * 8 + 2 * t] = v1;
    }
}

// ---------------------------------------------------------------------------
extern "C" void kernel_launch(void* const* d_in, const int* in_sizes, int n_in,
                              void* d_out, int out_size)
{
    const float* x    = (const float*)d_in[0];
    const float* Wq   = (const float*)d_in[1];
    const float* Wk   = (const float*)d_in[2];
    const float* Wv   = (const float*)d_in[3];
    const float* Wout = (const float*)d_in[4];
    float* out = (float*)d_out;

    cudaFuncSetAttribute(mma_gemm,
                         cudaFuncAttributeMaxDynamicSharedMemorySize, GEMM_SMEM);
    cudaFuncSetAttribute(flash_kernel,
                         cudaFuncAttributeMaxDynamicSharedMemorySize, FL_SMEM);

    // 0) one-time tf32 rounding of operands (Wq pre-scaled)
    prep_kernel<<<dim3(512, 5), 256>>>(x, Wq, Wk, Wv, Wout);

    // 1) QKV: scattered into [b][h][l][e], tf32-rounded
    mma_gemm<<<dim3(8, 32, 3), 256, GEMM_SMEM>>>(nullptr, 0);

    // 2) Flash attention (tf32 tensor cores)
    flash_kernel<<<dim3(Lc / 128, Bc * Hc), 256, FL_SMEM>>>();

    // 3) Output projection
    mma_gemm<<<dim3(8, 32, 1), 256, GEMM_SMEM>>>(out, 1);
}

// round 11
// speedup vs baseline: 3.7096x; 1.0043x over previous
#include <cuda_runtime.h>
#include <math.h>
#include <stdint.h>

// Problem constants
#define Bc 2
#define Lc 2048
#define Dc 1024
#define Hc 16
#define Dhc 64
#define Mg (Bc*Lc)          // 4096

// Scratch
__device__ float g_q[(size_t)Bc*Hc*Lc*Dhc];
__device__ float g_k[(size_t)Bc*Hc*Lc*Dhc];
__device__ float g_v[(size_t)Bc*Hc*Lc*Dhc];
__device__ float g_o[(size_t)Bc*Lc*Dc];
__device__ float g_xc[(size_t)Mg*Dc];        // x, tf32-rounded
__device__ float g_wc[(size_t)4*Dc*Dc];      // W{q,k,v,o}, tf32-rounded (Wq pre-scaled)

// ---------------------------------------------------------------------------
// Helpers
// ---------------------------------------------------------------------------
__device__ __forceinline__ uint32_t f2tf32(float f) {
    uint32_t u;
    asm("cvt.rna.tf32.f32 %0, %1;" : "=r"(u) : "f"(f));
    return u;
}

__device__ __forceinline__ float ex2(float x) {
    float r;
    asm("ex2.approx.f32 %0, %1;" : "=f"(r) : "f"(x));
    return r;
}

__device__ __forceinline__ uint32_t smem_u32(const void* p) {
    uint32_t a;
    asm("{ .reg .u64 t; cvta.to.shared.u64 t, %1; cvt.u32.u64 %0, t; }"
        : "=r"(a) : "l"(p));
    return a;
}

__device__ __forceinline__ void cpa16(uint32_t s, const void* g) {
    asm volatile("cp.async.cg.shared.global [%0], [%1], 16;" :: "r"(s), "l"(g));
}
#define CP_COMMIT() asm volatile("cp.async.commit_group;" ::: "memory")
#define CP_WAIT(n)  asm volatile("cp.async.wait_group %0;" :: "n"(n) : "memory")

__device__ __forceinline__ void mma_tf32(float* c, const uint32_t* a, const uint32_t* b) {
    asm volatile(
        "mma.sync.aligned.m16n8k8.row.col.f32.tf32.tf32.f32 "
        "{%0,%1,%2,%3}, {%4,%5,%6,%7}, {%8,%9}, {%0,%1,%2,%3};"
        : "+f"(c[0]), "+f"(c[1]), "+f"(c[2]), "+f"(c[3])
        : "r"(a[0]), "r"(a[1]), "r"(a[2]), "r"(a[3]), "r"(b[0]), "r"(b[1]));
}

// ---------------------------------------------------------------------------
// Prep: tf32-round x and weights once. Wq gets (1/8)*log2(e) folded in.
// ---------------------------------------------------------------------------
__global__ __launch_bounds__(256)
void prep_kernel(const float* __restrict__ x, const float* __restrict__ Wq,
                 const float* __restrict__ Wk, const float* __restrict__ Wv,
                 const float* __restrict__ Wo)
{
    const int y = blockIdx.y;
    const float* src;
    float* dst;
    size_t n;
    float scale = 1.0f;
    if (y == 0) { src = x; dst = g_xc; n = (size_t)Mg * Dc; }
    else {
        src = (y == 1) ? Wq : (y == 2) ? Wk : (y == 3) ? Wv : Wo;
        dst = g_wc + (size_t)(y - 1) * 1048576;
        n = 1048576;
        if (y == 1) scale = 0.18033688011112042f;   // (1/8)*log2(e)
    }
    const size_t stride = (size_t)gridDim.x * 256 * 4;
    for (size_t i = ((size_t)blockIdx.x * 256 + threadIdx.x) * 4; i < n; i += stride) {
        float4 v = *(const float4*)(src + i);
        uint4 u;
        u.x = f2tf32(v.x * scale); u.y = f2tf32(v.y * scale);
        u.z = f2tf32(v.z * scale); u.w = f2tf32(v.w * scale);
        *(uint4*)(dst + i) = u;
    }
}

// ---------------------------------------------------------------------------
// cp.async 3-stage pipelined TF32 GEMM. C[M,N] = A[M,K]*B[K,N], K=1024.
// Block 256x128, 8 warps (4x2), warp tile 64x64, k-chunk 32.
// Per k-step: 32 LDS feed 32 MMAs (was 24:16).
// mode 0: A=g_xc, B=g_wc[z], scatter tf32-rounded into g_q/g_k/g_v
// mode 1: A=g_o,  B=g_wc[3], plain fp32 row-major out
// ---------------------------------------------------------------------------
#define SA 36
#define SB 136
#define A_ST_FL (256*SA)                 // 9216 floats
#define B_ST_FL (32*SB)                  // 4352 floats
#define STG_FL  (A_ST_FL + B_ST_FL)      // 13568
#define STG_BYTES (STG_FL*4)             // 54272
#define GEMM_SMEM (3*STG_BYTES)          // 162816 B

__global__ __launch_bounds__(256, 1)
void mma_gemm(float* __restrict__ Dst, int mode)
{
    extern __shared__ float sm[];
    const uint32_t sb = smem_u32(sm);

    const int tid = threadIdx.x;
    const int lane = tid & 31, wid = tid >> 5;
    const int g = lane >> 2, t = lane & 3;
    const int wr = wid >> 1, wc = wid & 1;

    const int n0 = blockIdx.x * 128;
    const int m0 = blockIdx.y * 256;
    const int z  = blockIdx.z;

    const float* A = (mode == 0) ? g_xc : g_o;
    const float* B = g_wc + (size_t)((mode == 0) ? z : 3) * 1048576;

    const float* Agp = A + (size_t)(m0 + (tid >> 3)) * 1024 + (tid & 7) * 4;
    const float* Bgp = B + (size_t)(tid >> 5) * 1024 + n0 + (tid & 31) * 4;

    const uint32_t aoff = (uint32_t)(tid >> 3) * (SA * 4) + (tid & 7) * 16;
    const uint32_t boff = (uint32_t)(A_ST_FL * 4) + (uint32_t)(tid >> 5) * (SB * 4)
                        + (tid & 31) * 16;

#define G_ISSUE(ch) do { \
    const uint32_t st_ = sb + (uint32_t)((ch) % 3) * STG_BYTES; \
    const float* ag_ = Agp + (ch) * 32; \
    const float* bg_ = Bgp + (size_t)(ch) * 32 * 1024; \
    _Pragma("unroll") \
    for (int i_ = 0; i_ < 8; i_++) \
        cpa16(st_ + aoff + i_ * 32 * (SA * 4), ag_ + (size_t)i_ * 32 * 1024); \
    _Pragma("unroll") \
    for (int i_ = 0; i_ < 4; i_++) \
        cpa16(st_ + boff + i_ * 8 * (SB * 4), bg_ + (size_t)i_ * 8 * 1024); \
} while (0)

    float c[4][8][4];
#pragma unroll
    for (int mi = 0; mi < 4; mi++)
#pragma unroll
        for (int ni = 0; ni < 8; ni++)
#pragma unroll
            for (int q = 0; q < 4; q++) c[mi][ni][q] = 0.f;

    G_ISSUE(0); CP_COMMIT();
    G_ISSUE(1); CP_COMMIT();

    const int mbase = 64 * wr, nbase = 64 * wc;

    for (int ch = 0; ch < 32; ch++) {
        CP_WAIT(1);
        __syncthreads();                    // stage ch visible; compute ch-1 done
        if (ch + 2 < 32) G_ISSUE(ch + 2);   // into buffer consumed at ch-1
        CP_COMMIT();

        const float* as = sm + (ch % 3) * STG_FL;
        const float* bs = as + A_ST_FL;
#pragma unroll
        for (int ks = 0; ks < 4; ks++) {
            const int kk = ks * 8;
            uint32_t af[4][4];
#pragma unroll
            for (int mi = 0; mi < 4; mi++) {
                const int r0 = (mbase + 16*mi + g) * SA + kk + t;
                af[mi][0] = __float_as_uint(as[r0]);
                af[mi][1] = __float_as_uint(as[r0 + 8*SA]);
                af[mi][2] = __float_as_uint(as[r0 + 4]);
                af[mi][3] = __float_as_uint(as[r0 + 8*SA + 4]);
            }
            uint32_t bf[8][2];
#pragma unroll
            for (int ni = 0; ni < 8; ni++) {
                const int b0 = (kk + t) * SB + nbase + 8*ni + g;
                bf[ni][0] = __float_as_uint(bs[b0]);
                bf[ni][1] = __float_as_uint(bs[b0 + 4*SB]);
            }
#pragma unroll
            for (int mi = 0; mi < 4; mi++)
#pragma unroll
                for (int ni = 0; ni < 8; ni++)
                    mma_tf32(c[mi][ni], af[mi], bf[ni]);
        }
    }

    // Epilogue. mode 0: tf32-round (consumers feed mma directly).
    float* gz = (mode == 0) ? ((z == 0) ? g_q : (z == 1) ? g_k : g_v) : Dst;
#pragma unroll
    for (int mi = 0; mi < 4; mi++) {
#pragma unroll
        for (int half = 0; half < 2; half++) {
            const int mglob = m0 + mbase + 16*mi + g + 8*half;
#pragma unroll
            for (int ni = 0; ni < 8; ni++) {
                const int nglob = n0 + nbase + 8*ni + 2*t;
                float2 v;
                v.x = c[mi][ni][2*half + 0];
                v.y = c[mi][ni][2*half + 1];
                if (mode == 0) {
                    v.x = __uint_as_float(f2tf32(v.x));
                    v.y = __uint_as_float(f2tf32(v.y));
                    const int b = mglob >> 11, l = mglob & 2047;
                    const int h = nglob >> 6, e = nglob & 63;
                    *(float2*)&gz[(((size_t)(b*Hc + h) * Lc + l) << 6) + e] = v;
                } else {
                    *(float2*)&gz[(size_t)mglob * 1024 + nglob] = v;
                }
            }
        }
    }
}

// ---------------------------------------------------------------------------
// TF32 tensor-core causal flash attention. Inputs pre-rounded tf32 (Q
// pre-scaled). K and V in separate cp.async groups: V load overlaps QK^T.
// Block: 128 q-rows (8 warps x 16), K-tile 64.
// ---------------------------------------------------------------------------
#define SQf 68
#define SKf 68
#define SVf 72
#define SPf 68
#define QS_OFF 0
#define KS_OFF (128*SQf)                 // 8704
#define VS_OFF (KS_OFF + 64*SKf)         // 13056
#define PS_OFF (VS_OFF + 64*SVf)         // 17664
#define FL_FLOATS (PS_OFF + 128*SPf)     // 26368
#define FL_SMEM (FL_FLOATS * 4)          // 105472 B

__global__ __launch_bounds__(256, 2)
void flash_kernel()
{
    extern __shared__ float sm[];
    const uint32_t sb = smem_u32(sm);
    float* Qs = sm + QS_OFF;
    float* Ks = sm + KS_OFF;
    float* Vs = sm + VS_OFF;
    float* Ps = sm + PS_OFF;

    const int qt = gridDim.x - 1 - blockIdx.x;   // heavy tiles first
    const int bh = blockIdx.y;
    const int tid = threadIdx.x;
    const int lane = tid & 31, wid = tid >> 5;
    const int g = lane >> 2, t = lane & 3;
    const int wq0 = wid * 16;

    const float* qb = g_q + (size_t)bh * Lc * Dhc;
    const float* kb = g_k + (size_t)bh * Lc * Dhc;
    const float* vb = g_v + (size_t)bh * Lc * Dhc;

    // Q tile (128 x 64) via cp.async (already scaled + tf32)
#pragma unroll
    for (int it = 0; it < 8; it++) {
        const int idx = it * 256 + tid;
        const int r = idx >> 4, c4 = (idx & 15) * 4;
        cpa16(sb + (uint32_t)(r * SQf + c4) * 4,
              qb + (size_t)(qt * 128 + r) * 64 + c4);
    }
    CP_COMMIT();

    float m2[2] = {-1e30f, -1e30f};
    float lsum[2] = {0.f, 0.f};
    float o[8][4];
#pragma unroll
    for (int ni = 0; ni < 8; ni++)
#pragma unroll
        for (int q = 0; q < 4; q++) o[ni][q] = 0.f;

    const int kend = 2 * qt + 1;
    for (int kt = 0; kt <= kend; kt++) {
        __syncthreads();   // prior iter's K/V reads complete
        // K group
#pragma unroll
        for (int it = 0; it < 4; it++) {
            const int idx = it * 256 + tid;
            const int r = idx >> 4, c4 = (idx & 15) * 4;
            cpa16(sb + (uint32_t)(KS_OFF + r * SKf + c4) * 4,
                  kb + (size_t)(kt * 64 + r) * 64 + c4);
        }
        CP_COMMIT();
        // V group (completes while we compute S)
#pragma unroll
        for (int it = 0; it < 4; it++) {
            const int idx = it * 256 + tid;
            const int r = idx >> 4, c4 = (idx & 15) * 4;
            cpa16(sb + (uint32_t)(VS_OFF + r * SVf + c4) * 4,
                  vb + (size_t)(kt * 64 + r) * 64 + c4);
        }
        CP_COMMIT();

        CP_WAIT(1);        // K ready (V may still be in flight)
        __syncthreads();

        // S = Q K^T  (warp: 16 x 64, k=64)
        float s[8][4];
#pragma unroll
        for (int ni = 0; ni < 8; ni++)
#pragma unroll
            for (int q = 0; q < 4; q++) s[ni][q] = 0.f;

#pragma unroll
        for (int ks = 0; ks < 8; ks++) {
            const int k0 = ks * 8;
            uint32_t a[4];
            a[0] = __float_as_uint(Qs[(wq0 + g) * SQf + k0 + t]);
            a[1] = __float_as_uint(Qs[(wq0 + g + 8) * SQf + k0 + t]);
            a[2] = __float_as_uint(Qs[(wq0 + g) * SQf + k0 + t + 4]);
            a[3] = __float_as_uint(Qs[(wq0 + g + 8) * SQf + k0 + t + 4]);
#pragma unroll
            for (int ni = 0; ni < 8; ni++) {
                uint32_t b[2];
                b[0] = __float_as_uint(Ks[(ni * 8 + g) * SKf + k0 + t]);
                b[1] = __float_as_uint(Ks[(ni * 8 + g) * SKf + k0 + t + 4]);
                mma_tf32(s[ni], a, b);
            }
        }

        // Causal mask (near-diagonal tiles only)
        if (kt >= 2 * qt) {
            const int q0r = qt * 128 + wq0 + g;
#pragma unroll
            for (int ni = 0; ni < 8; ni++) {
                const int key0 = kt * 64 + ni * 8 + 2 * t;
                if (key0     > q0r)     s[ni][0] = -1e30f;
                if (key0 + 1 > q0r)     s[ni][1] = -1e30f;
                if (key0     > q0r + 8) s[ni][2] = -1e30f;
                if (key0 + 1 > q0r + 8) s[ni][3] = -1e30f;
            }
        }

        // Online softmax (rows g, g+8; reduce over t-lanes via shfl).
        // Ps rows are warp-private -> __syncwarp ordering suffices.
        __syncwarp();
#pragma unroll
        for (int rr = 0; rr < 2; rr++) {
            float mx = -1e30f;
#pragma unroll
            for (int ni = 0; ni < 8; ni++)
                mx = fmaxf(mx, fmaxf(s[ni][2*rr], s[ni][2*rr + 1]));
            mx = fmaxf(mx, __shfl_xor_sync(0xffffffffu, mx, 1));
            mx = fmaxf(mx, __shfl_xor_sync(0xffffffffu, mx, 2));
            const float mnew = fmaxf(m2[rr], mx);
            const float corr = ex2(m2[rr] - mnew);
            float rs = 0.f;
#pragma unroll
            for (int ni = 0; ni < 8; ni++) {
                const float p0 = ex2(s[ni][2*rr]     - mnew);
                const float p1 = ex2(s[ni][2*rr + 1] - mnew);
                rs += p0 + p1;
                uint2 pw;
                pw.x = f2tf32(p0); pw.y = f2tf32(p1);
                *(uint2*)(Ps + (wq0 + g + 8*rr) * SPf + ni * 8 + 2 * t) = pw;
            }
            rs += __shfl_xor_sync(0xffffffffu, rs, 1);
            rs += __shfl_xor_sync(0xffffffffu, rs, 2);
            lsum[rr] = lsum[rr] * corr + rs;
            m2[rr] = mnew;
#pragma unroll
            for (int ni = 0; ni < 8; ni++) {
                o[ni][2*rr]     *= corr;
                o[ni][2*rr + 1] *= corr;
            }
        }
        __syncwarp();

        CP_WAIT(0);        // V ready
        __syncthreads();

        // O += P V
#pragma unroll
        for (int ks = 0; ks < 8; ks++) {
            const int k0 = ks * 8;
            uint32_t a[4];
            a[0] = __float_as_uint(Ps[(wq0 + g) * SPf + k0 + t]);
            a[1] = __float_as_uint(Ps[(wq0 + g + 8) * SPf + k0 + t]);
            a[2] = __float_as_uint(Ps[(wq0 + g) * SPf + k0 + t + 4]);
            a[3] = __float_as_uint(Ps[(wq0 + g + 8) * SPf + k0 + t + 4]);
#pragma unroll
            for (int ni = 0; ni < 8; ni++) {
                uint32_t b[2];
                b[0] = __float_as_uint(Vs[(k0 + t) * SVf + ni * 8 + g]);
                b[1] = __float_as_uint(Vs[(k0 + t + 4) * SVf + ni * 8 + g]);
                mma_tf32(o[ni], a, b);
            }
        }
    }

    // Epilogue: normalize, tf32-round (feeds out-proj mma), write g_o
    const float inv0 = 1.0f / lsum[0];
    const float inv1 = 1.0f / lsum[1];
    const int b = bh >> 4, h = bh & 15;
    const int q0 = qt * 128 + wq0 + g;
    const size_t base0 = ((size_t)(b * Lc + q0)) * Dc + h * Dhc;
    const size_t base1 = base0 + (size_t)8 * Dc;
#pragma unroll
    for (int ni = 0; ni < 8; ni++) {
        float2 v0, v1;
        v0.x = __uint_as_float(f2tf32(o[ni][0] * inv0));
        v0.y = __uint_as_float(f2tf32(o[ni][1] * inv0));
        v1.x = __uint_as_float(f2tf32(o[ni][2] * inv1));
        v1.y = __uint_as_float(f2tf32(o[ni][3] * inv1));
        *(float2*)&g_o[base0 + ni * 8 + 2 * t] = v0;
        *(float2*)&g_o[base1 + ni * 8 + 2 * t] = v1;
    }
}

// ---------------------------------------------------------------------------
extern "C" void kernel_launch(void* const* d_in, const int* in_sizes, int n_in,
                              void* d_out, int out_size)
{
    const float* x    = (const float*)d_in[0];
    const float* Wq   = (const float*)d_in[1];
    const float* Wk   = (const float*)d_in[2];
    const float* Wv   = (const float*)d_in[3];
    const float* Wout = (const float*)d_in[4];
    float* out = (float*)d_out;

    cudaFuncSetAttribute(mma_gemm,
                         cudaFuncAttributeMaxDynamicSharedMemorySize, GEMM_SMEM);
    cudaFuncSetAttribute(flash_kernel,
                         cudaFuncAttributeMaxDynamicSharedMemorySize, FL_SMEM);

    // 0) one-time tf32 rounding of operands (Wq pre-scaled)
    prep_kernel<<<dim3(512, 5), 256>>>(x, Wq, Wk, Wv, Wout);

    // 1) QKV: scattered into [b][h][l][e], tf32-rounded
    mma_gemm<<<dim3(8, 16, 3), 256, GEMM_SMEM>>>(nullptr, 0);

    // 2) Flash attention (tf32 tensor cores)
    flash_kernel<<<dim3(Lc / 128, Bc * Hc), 256, FL_SMEM>>>();

    // 3) Output projection
    mma_gemm<<<dim3(8, 16, 1), 256, GEMM_SMEM>>>(out, 1);
}